// round 1
// baseline (speedup 1.0000x reference)
#include <cuda_runtime.h>

// ---------------------------------------------------------------------------
// SparseConvolutionDownsample: rulebook sparse conv + BN + LeakyReLU
//   feats [1048576, 64] f32, W [4, 64, 128] f32, gamma/beta [128] f32,
//   in_idx/out_idx [4, 262144] i32, out [262144, 128] f32
// ---------------------------------------------------------------------------

namespace {
constexpr int C_IN   = 64;
constexpr int C_OUT  = 128;
constexpr int KK     = 4;
constexpr int PNUM   = 262144;
constexpr int N_OUTR = 262144;
constexpr float BN_EPS = 1e-4f;
constexpr float LEAK   = 0.333f;
}

// per-channel running sums: [0..127] = sum, [128..255] = sum of squares
__device__ float g_stats[2 * C_OUT];

// packed f32x2 FMA (FFMA2) — only reachable via PTX on sm_103a
__device__ __forceinline__ void ffma2(unsigned long long& d,
                                      unsigned long long a,
                                      unsigned long long b) {
    asm("fma.rn.f32x2 %0, %1, %2, %0;" : "+l"(d) : "l"(a), "l"(b));
}

// ---------------------------------------------------------------------------
// Kernel 0: zero the accumulator + zero BN stats
// ---------------------------------------------------------------------------
__global__ void zero_kernel(float4* __restrict__ out) {
    const size_t n = (size_t)N_OUTR * C_OUT / 4;
    const size_t stride = (size_t)gridDim.x * blockDim.x;
    const float4 z = make_float4(0.f, 0.f, 0.f, 0.f);
    for (size_t i = (size_t)blockIdx.x * blockDim.x + threadIdx.x; i < n; i += stride)
        out[i] = z;
    if (blockIdx.x == 0 && threadIdx.x < 2 * C_OUT)
        g_stats[threadIdx.x] = 0.f;
}

// ---------------------------------------------------------------------------
// Kernel 1: fused gather -> GEMV -> scatter-add (atomic)
//
// Block = 256 threads = 8 warps = 4 (row-pair) x 2 (channel half).
// Each lane owns an adjacent channel pair (chBase, chBase+1):
//   - W[k] column pair held in 64 packed-f32x2 registers (128 regs)
//   - gathered feature row staged in SMEM pre-duplicated as {v,v} 8B words,
//     so the inner loop is: LDS.64 broadcast + FFMA2  (64 iterations)
//   - next row batch prefetched via LDG while computing the current one
// ---------------------------------------------------------------------------
__global__ __launch_bounds__(256, 1) void spconv_kernel(
    const float* __restrict__ feats,
    const float* __restrict__ W,
    const int*   __restrict__ in_idx,
    const int*   __restrict__ out_idx,
    float*       __restrict__ out)
{
    __shared__ unsigned long long sfeat[4][C_IN];   // 4 rows x 64 duplicated pairs

    const int k      = blockIdx.y;
    const int tid    = threadIdx.x;
    const int lane   = tid & 31;
    const int warp   = tid >> 5;
    const int pairId = warp >> 1;   // which of the 4 staged rows
    const int half   = warp & 1;    // channel half (0..63 / 64..127)
    const int chBase = half * 64 + 2 * lane;

    // ---- load W[k] column-pair into registers (fully unrolled -> regs) ----
    const float* Wk = W + k * C_IN * C_OUT;
    unsigned long long wreg[C_IN];
#pragma unroll
    for (int i = 0; i < C_IN; i++) {
        float2 w = *reinterpret_cast<const float2*>(Wk + i * C_OUT + chBase);
        wreg[i] = ((unsigned long long)__float_as_uint(w.y) << 32)
                |  (unsigned long long)__float_as_uint(w.x);
    }

    const int* inI  = in_idx  + k * PNUM;
    const int* outI = out_idx + k * PNUM;

    // staging mapping: thread t loads element (t&63) of row (t>>6)
    const int srow   = tid >> 6;
    const int scol   = tid & 63;
    const int stride = gridDim.x * 4;

    // prologue gather for the first batch
    int sp = blockIdx.x * 4 + srow;
    float v = 0.f;
    if (sp < PNUM)
        v = __ldg(&feats[(size_t)__ldg(&inI[sp]) * C_IN + scol]);

    for (int base = blockIdx.x * 4; base < PNUM; base += stride) {
        // publish current batch into SMEM (duplicated for f32x2 broadcast)
        unsigned int vb = __float_as_uint(v);
        sfeat[srow][scol] = ((unsigned long long)vb << 32) | vb;
        __syncthreads();

        // prefetch next batch (LDG latency hidden under compute)
        int nsp = base + stride + srow;
        v = 0.f;
        if (nsp < PNUM)
            v = __ldg(&feats[(size_t)__ldg(&inI[nsp]) * C_IN + scol]);

        // compute: 64 x (LDS.64 broadcast + FFMA2), two accumulator chains
        int p = base + pairId;
        if (p < PNUM) {
            unsigned long long acc0 = 0ull, acc1 = 0ull;
#pragma unroll
            for (int i = 0; i < C_IN; i += 2) {
                ffma2(acc0, sfeat[pairId][i],     wreg[i]);
                ffma2(acc1, sfeat[pairId][i + 1], wreg[i + 1]);
            }
            float r0 = __uint_as_float((unsigned)(acc0 & 0xffffffffu))
                     + __uint_as_float((unsigned)(acc1 & 0xffffffffu));
            float r1 = __uint_as_float((unsigned)(acc0 >> 32))
                     + __uint_as_float((unsigned)(acc1 >> 32));

            size_t orow = (size_t)__ldg(&outI[p]);
            atomicAdd(&out[orow * C_OUT + chBase],     r0);
            atomicAdd(&out[orow * C_OUT + chBase + 1], r1);
        }
        __syncthreads();   // everyone done reading sfeat before next overwrite
    }
}

// ---------------------------------------------------------------------------
// Kernel 2: per-channel sum / sumsq (block-partial + global atomics)
// Block = 256 threads = 8 rows x 32 float4 channel-groups.
// ---------------------------------------------------------------------------
__global__ void bn_stats_kernel(const float4* __restrict__ out) {
    const int cg = threadIdx.x & 31;   // float4 channel group
    const int rs = threadIdx.x >> 5;   // row sub-slot 0..7
    const int rowsPerBlock = N_OUTR / gridDim.x;
    const int r0 = blockIdx.x * rowsPerBlock;

    float4 s  = make_float4(0.f, 0.f, 0.f, 0.f);
    float4 s2 = make_float4(0.f, 0.f, 0.f, 0.f);
    for (int r = r0 + rs; r < r0 + rowsPerBlock; r += 8) {
        float4 vv = out[(size_t)r * (C_OUT / 4) + cg];
        s.x += vv.x;  s.y += vv.y;  s.z += vv.z;  s.w += vv.w;
        s2.x += vv.x * vv.x;  s2.y += vv.y * vv.y;
        s2.z += vv.z * vv.z;  s2.w += vv.w * vv.w;
    }

    __shared__ float4 shs[256], shq[256];
    shs[threadIdx.x] = s;
    shq[threadIdx.x] = s2;
    __syncthreads();
#pragma unroll
    for (int off = 128; off >= 32; off >>= 1) {
        if (threadIdx.x < off) {
            float4 a = shs[threadIdx.x], b = shs[threadIdx.x + off];
            a.x += b.x; a.y += b.y; a.z += b.z; a.w += b.w;
            shs[threadIdx.x] = a;
            float4 c = shq[threadIdx.x], d = shq[threadIdx.x + off];
            c.x += d.x; c.y += d.y; c.z += d.z; c.w += d.w;
            shq[threadIdx.x] = c;
        }
        __syncthreads();
    }
    if (threadIdx.x < 32) {
        float4 a = shs[threadIdx.x], c = shq[threadIdx.x];
        int c0 = threadIdx.x * 4;
        atomicAdd(&g_stats[c0 + 0], a.x);
        atomicAdd(&g_stats[c0 + 1], a.y);
        atomicAdd(&g_stats[c0 + 2], a.z);
        atomicAdd(&g_stats[c0 + 3], a.w);
        atomicAdd(&g_stats[C_OUT + c0 + 0], c.x);
        atomicAdd(&g_stats[C_OUT + c0 + 1], c.y);
        atomicAdd(&g_stats[C_OUT + c0 + 2], c.z);
        atomicAdd(&g_stats[C_OUT + c0 + 3], c.w);
    }
}

// ---------------------------------------------------------------------------
// Kernel 3: normalize + LeakyReLU (in place, float4)
// ---------------------------------------------------------------------------
__global__ void bn_norm_kernel(float4* __restrict__ out,
                               const float* __restrict__ gamma,
                               const float* __restrict__ beta) {
    __shared__ float sc[C_OUT], sf[C_OUT];
    if (threadIdx.x < C_OUT) {
        int c = threadIdx.x;
        const float inv = 1.f / (float)N_OUTR;
        float mean = g_stats[c] * inv;
        float var  = g_stats[C_OUT + c] * inv - mean * mean;
        float s    = gamma[c] * rsqrtf(var + BN_EPS);
        sc[c] = s;
        sf[c] = beta[c] - mean * s;
    }
    __syncthreads();

    const size_t n = (size_t)N_OUTR * (C_OUT / 4);
    const size_t stride = (size_t)gridDim.x * blockDim.x;
    for (size_t i = (size_t)blockIdx.x * blockDim.x + threadIdx.x; i < n; i += stride) {
        int c0 = ((int)(i & 31)) * 4;
        float4 v = out[i];
        v.x = v.x * sc[c0 + 0] + sf[c0 + 0];
        v.y = v.y * sc[c0 + 1] + sf[c0 + 1];
        v.z = v.z * sc[c0 + 2] + sf[c0 + 2];
        v.w = v.w * sc[c0 + 3] + sf[c0 + 3];
        v.x = (v.x >= 0.f) ? v.x : v.x * LEAK;
        v.y = (v.y >= 0.f) ? v.y : v.y * LEAK;
        v.z = (v.z >= 0.f) ? v.z : v.z * LEAK;
        v.w = (v.w >= 0.f) ? v.w : v.w * LEAK;
        out[i] = v;
    }
}

// ---------------------------------------------------------------------------
// Launch: inputs per metadata order:
//   0 feats, 1 W, 2 gamma, 3 beta, 4 in_idx, 5 out_idx, 6 n_out (ignored)
// ---------------------------------------------------------------------------
extern "C" void kernel_launch(void* const* d_in, const int* in_sizes, int n_in,
                              void* d_out, int out_size) {
    const float* feats   = (const float*)d_in[0];
    const float* W       = (const float*)d_in[1];
    const float* gamma   = (const float*)d_in[2];
    const float* beta    = (const float*)d_in[3];
    const int*   in_idx  = (const int*)d_in[4];
    const int*   out_idx = (const int*)d_in[5];
    float* out = (float*)d_out;

    zero_kernel<<<1024, 256>>>((float4*)out);
    spconv_kernel<<<dim3(152, 4), 256>>>(feats, W, in_idx, out_idx, out);
    bn_stats_kernel<<<256, 256>>>((const float4*)out);
    bn_norm_kernel<<<1024, 256>>>((float4*)out, gamma, beta);
}

// round 2
// speedup vs baseline: 2.4124x; 2.4124x over previous
#include <cuda_runtime.h>

// ---------------------------------------------------------------------------
// SparseConvolutionDownsample: rulebook sparse conv + BN + LeakyReLU
//   feats [1048576, 64] f32, W [4, 64, 128] f32, gamma/beta [128] f32,
//   in_idx/out_idx [4, 262144] i32, out [262144, 128] f32
// ---------------------------------------------------------------------------

namespace {
constexpr int C_IN   = 64;
constexpr int C_OUT  = 128;
constexpr int PNUM   = 262144;
constexpr int N_OUTR = 262144;
constexpr float BN_EPS = 1e-4f;
constexpr float LEAK   = 0.333f;

constexpr int P_STRIDE = 152;                 // warps per (k, half)
constexpr int NUM_T    = (PNUM + P_STRIDE - 1) / P_STRIDE;  // 1725 rows max per warp
constexpr int NUM_B    = (NUM_T + 3) / 4;     // 432 batches of 4 rows
}

// per-channel running sums: [0..127] = sum, [128..255] = sum of squares
__device__ float g_stats[2 * C_OUT];

// packed f32x2 FMA (FFMA2) — PTX-only on sm_103a
__device__ __forceinline__ void ffma2(unsigned long long& d,
                                      unsigned long long a,
                                      unsigned long long b) {
    asm("fma.rn.f32x2 %0, %1, %2, %0;" : "+l"(d) : "l"(a), "l"(b));
}
__device__ __forceinline__ unsigned long long dup2(float x) {
    unsigned u = __float_as_uint(x);
    return ((unsigned long long)u << 32) | u;
}
__device__ __forceinline__ float lo32(unsigned long long v) {
    return __uint_as_float((unsigned)(v & 0xffffffffu));
}
__device__ __forceinline__ float hi32(unsigned long long v) {
    return __uint_as_float((unsigned)(v >> 32));
}

// ---------------------------------------------------------------------------
// Kernel 0: zero the accumulator + zero BN stats
// ---------------------------------------------------------------------------
__global__ void zero_kernel(float4* __restrict__ out) {
    const size_t n = (size_t)N_OUTR * C_OUT / 4;
    const size_t stride = (size_t)gridDim.x * blockDim.x;
    const float4 z = make_float4(0.f, 0.f, 0.f, 0.f);
    for (size_t i = (size_t)blockIdx.x * blockDim.x + threadIdx.x; i < n; i += stride)
        out[i] = z;
    if (blockIdx.x == 0 && threadIdx.x < 2 * C_OUT)
        g_stats[threadIdx.x] = 0.f;
}

// ---------------------------------------------------------------------------
// Kernel 1: warp-autonomous gather -> GEMV -> v2-atomic scatter
//
// Block = 128 threads = 4 warps. Warp gw = blockIdx.x*4 + warp:
//   half = gw & 1 (channels 0..63 or 64..127), p0 = gw >> 1, p stride 152.
// Each lane owns channel pair (chBase, chBase+1); W[k] column-pair in 128 regs.
// Rows processed in batches of 4 with one-batch-ahead gather prefetch.
// Inner loop per row: 32 x LDS.128 (two duplicated f32 pairs) + 64 x FFMA2,
// 4 independent accumulator chains, then ONE red.global.add.v2.f32.
// Only __syncwarp (per-warp SMEM slot) — no block barriers.
// ---------------------------------------------------------------------------
__global__ __launch_bounds__(128, 2) void spconv_kernel(
    const float* __restrict__ feats,
    const float* __restrict__ W,
    const int*   __restrict__ in_idx,
    const int*   __restrict__ out_idx,
    float*       __restrict__ out)
{
    // [warp][row-in-batch][col-pair]: {dup(v_{2j}), dup(v_{2j+1})} per entry
    __shared__ ulonglong2 sfeat[4][4][32];   // 8 KB

    const int k    = blockIdx.y;
    const int w    = threadIdx.x >> 5;
    const int lane = threadIdx.x & 31;
    const int gw   = blockIdx.x * 4 + w;     // 0..303
    const int half = gw & 1;
    const int p0   = gw >> 1;                // 0..151
    const int chBase = half * 64 + 2 * lane;

    // ---- W[k] column-pair -> 64 packed f32x2 registers ----
    const float* Wk = W + k * C_IN * C_OUT;
    unsigned long long wreg[C_IN];
#pragma unroll
    for (int i = 0; i < C_IN; i++) {
        float2 ww = *reinterpret_cast<const float2*>(Wk + i * C_OUT + chBase);
        wreg[i] = ((unsigned long long)__float_as_uint(ww.y) << 32)
                |  (unsigned long long)__float_as_uint(ww.x);
    }

    const int* inI  = in_idx  + k * PNUM;
    const int* outI = out_idx + k * PNUM;

    float2 v[4];
    int    oidx[4];

    // gather one row (lane loads its float2 of the feature row); self-guarded
    auto load_row = [&](int t, float2& vv, int& oo) {
        int p = p0 + t * P_STRIDE;
        if (p < PNUM) {
            int ii = __ldg(&inI[p]);
            vv = __ldg(reinterpret_cast<const float2*>(
                     &feats[(size_t)ii * C_IN + 2 * lane]));
            oo = __ldg(&outI[p]);
        } else {
            vv = make_float2(0.f, 0.f);
            oo = 0;
        }
    };

    // prologue: batch 0
#pragma unroll
    for (int u = 0; u < 4; u++) load_row(u, v[u], oidx[u]);

    for (int b = 0; b < NUM_B; b++) {
        // publish current batch (duplicated pairs, 16B per lane per row)
#pragma unroll
        for (int u = 0; u < 4; u++)
            sfeat[w][u][lane] = make_ulonglong2(dup2(v[u].x), dup2(v[u].y));

        // snapshot out-row ids before the prefetch clobbers them
        int oo0 = oidx[0], oo1 = oidx[1], oo2 = oidx[2], oo3 = oidx[3];

        __syncwarp();

        // prefetch next batch (latency hidden under this batch's compute)
#pragma unroll
        for (int u = 0; u < 4; u++) load_row(4 * (b + 1) + u, v[u], oidx[u]);

        // compute the 4 staged rows
#pragma unroll
        for (int u = 0; u < 4; u++) {
            const int t = 4 * b + u;
            const int p = p0 + t * P_STRIDE;
            if (p < PNUM) {
                const ulonglong2* sf = sfeat[w][u];
                unsigned long long a0 = 0ull, a1 = 0ull, a2 = 0ull, a3 = 0ull;
#pragma unroll
                for (int j = 0; j < 32; j += 2) {
                    ulonglong2 q0 = sf[j];
                    ulonglong2 q1 = sf[j + 1];
                    ffma2(a0, q0.x, wreg[2 * j]);
                    ffma2(a1, q0.y, wreg[2 * j + 1]);
                    ffma2(a2, q1.x, wreg[2 * j + 2]);
                    ffma2(a3, q1.y, wreg[2 * j + 3]);
                }
                float r0 = (lo32(a0) + lo32(a1)) + (lo32(a2) + lo32(a3));
                float r1 = (hi32(a0) + hi32(a1)) + (hi32(a2) + hi32(a3));

                int oo = (u == 0) ? oo0 : (u == 1) ? oo1 : (u == 2) ? oo2 : oo3;
                float* addr = out + (size_t)oo * C_OUT + chBase;
                asm volatile("red.global.add.v2.f32 [%0], {%1, %2};"
                             :: "l"(addr), "f"(r0), "f"(r1) : "memory");
            }
        }
        __syncwarp();
    }
}

// ---------------------------------------------------------------------------
// Kernel 2: per-channel sum / sumsq (block-partial + global atomics)
// ---------------------------------------------------------------------------
__global__ void bn_stats_kernel(const float4* __restrict__ out) {
    const int cg = threadIdx.x & 31;   // float4 channel group
    const int rs = threadIdx.x >> 5;   // row sub-slot 0..7
    const int rowsPerBlock = N_OUTR / gridDim.x;
    const int r0 = blockIdx.x * rowsPerBlock;

    float4 s  = make_float4(0.f, 0.f, 0.f, 0.f);
    float4 s2 = make_float4(0.f, 0.f, 0.f, 0.f);
    for (int r = r0 + rs; r < r0 + rowsPerBlock; r += 8) {
        float4 vv = out[(size_t)r * (C_OUT / 4) + cg];
        s.x += vv.x;  s.y += vv.y;  s.z += vv.z;  s.w += vv.w;
        s2.x += vv.x * vv.x;  s2.y += vv.y * vv.y;
        s2.z += vv.z * vv.z;  s2.w += vv.w * vv.w;
    }

    __shared__ float4 shs[256], shq[256];
    shs[threadIdx.x] = s;
    shq[threadIdx.x] = s2;
    __syncthreads();
#pragma unroll
    for (int off = 128; off >= 32; off >>= 1) {
        if (threadIdx.x < off) {
            float4 a = shs[threadIdx.x], b = shs[threadIdx.x + off];
            a.x += b.x; a.y += b.y; a.z += b.z; a.w += b.w;
            shs[threadIdx.x] = a;
            float4 c = shq[threadIdx.x], d = shq[threadIdx.x + off];
            c.x += d.x; c.y += d.y; c.z += d.z; c.w += d.w;
            shq[threadIdx.x] = c;
        }
        __syncthreads();
    }
    if (threadIdx.x < 32) {
        float4 a = shs[threadIdx.x], c = shq[threadIdx.x];
        int c0 = threadIdx.x * 4;
        atomicAdd(&g_stats[c0 + 0], a.x);
        atomicAdd(&g_stats[c0 + 1], a.y);
        atomicAdd(&g_stats[c0 + 2], a.z);
        atomicAdd(&g_stats[c0 + 3], a.w);
        atomicAdd(&g_stats[C_OUT + c0 + 0], c.x);
        atomicAdd(&g_stats[C_OUT + c0 + 1], c.y);
        atomicAdd(&g_stats[C_OUT + c0 + 2], c.z);
        atomicAdd(&g_stats[C_OUT + c0 + 3], c.w);
    }
}

// ---------------------------------------------------------------------------
// Kernel 3: normalize + LeakyReLU (in place, float4)
// ---------------------------------------------------------------------------
__global__ void bn_norm_kernel(float4* __restrict__ out,
                               const float* __restrict__ gamma,
                               const float* __restrict__ beta) {
    __shared__ float sc[C_OUT], sf[C_OUT];
    if (threadIdx.x < C_OUT) {
        int c = threadIdx.x;
        const float inv = 1.f / (float)N_OUTR;
        float mean = g_stats[c] * inv;
        float var  = g_stats[C_OUT + c] * inv - mean * mean;
        float s    = gamma[c] * rsqrtf(var + BN_EPS);
        sc[c] = s;
        sf[c] = beta[c] - mean * s;
    }
    __syncthreads();

    const size_t n = (size_t)N_OUTR * (C_OUT / 4);
    const size_t stride = (size_t)gridDim.x * blockDim.x;
    for (size_t i = (size_t)blockIdx.x * blockDim.x + threadIdx.x; i < n; i += stride) {
        int c0 = ((int)(i & 31)) * 4;
        float4 v = out[i];
        v.x = v.x * sc[c0 + 0] + sf[c0 + 0];
        v.y = v.y * sc[c0 + 1] + sf[c0 + 1];
        v.z = v.z * sc[c0 + 2] + sf[c0 + 2];
        v.w = v.w * sc[c0 + 3] + sf[c0 + 3];
        v.x = (v.x >= 0.f) ? v.x : v.x * LEAK;
        v.y = (v.y >= 0.f) ? v.y : v.y * LEAK;
        v.z = (v.z >= 0.f) ? v.z : v.z * LEAK;
        v.w = (v.w >= 0.f) ? v.w : v.w * LEAK;
        out[i] = v;
    }
}

// ---------------------------------------------------------------------------
// Launch: inputs per metadata order:
//   0 feats, 1 W, 2 gamma, 3 beta, 4 in_idx, 5 out_idx, 6 n_out (ignored)
// ---------------------------------------------------------------------------
extern "C" void kernel_launch(void* const* d_in, const int* in_sizes, int n_in,
                              void* d_out, int out_size) {
    const float* feats   = (const float*)d_in[0];
    const float* W       = (const float*)d_in[1];
    const float* gamma   = (const float*)d_in[2];
    const float* beta    = (const float*)d_in[3];
    const int*   in_idx  = (const int*)d_in[4];
    const int*   out_idx = (const int*)d_in[5];
    float* out = (float*)d_out;

    zero_kernel<<<1024, 256>>>((float4*)out);
    spconv_kernel<<<dim3(76, 4), 128>>>(feats, W, in_idx, out_idx, out);
    bn_stats_kernel<<<256, 256>>>((const float4*)out);
    bn_norm_kernel<<<1024, 256>>>((float4*)out, gamma, beta);
}